// round 17
// baseline (speedup 1.0000x reference)
#include <cuda_runtime.h>
#include <math.h>

#define BB 128
#define SS 16
#define EE 512
#define RR 1000
#define G3 1536
#define NSCALE 0.04419417382415922f

// ---- device scratch (static, no allocations) ----
__device__ float GI_emb[RR * G3];
__device__ float H1_emb[RR * EE];
__device__ float GHH_emb[RR * G3];
__device__ float g_tscr[RR * G3];
__device__ float g_Krel[RR * EE];
__device__ float g_KW[RR * EE];
__device__ float g_cs[RR];
__device__ float g_AT[EE * EE];
__device__ float g_wvec[EE];
__device__ float g_c0[1];

__device__ float g_gi [BB * SS * G3];
__device__ float g_h1 [BB * SS * EE];
__device__ float g_ghh[BB * SS * G3];

__device__ int   g_src [BB * SS];
__device__ int   g_ord [BB * SS];
__device__ int   g_sel [BB];
__device__ int   g_dslot[BB];
__device__ float g_pscore[BB * SS];

__device__ float g_pair [BB * EE];
__device__ float g_newx [BB * EE];
__device__ float g_newh1[BB * EE];
__device__ float g_probp[BB * 1024];   // padded probs, [1000..1023] = 0
__device__ float g_pp[BB];             // prob of the pair key

// split-K partial buffers
__device__ float g_scp[4][BB * RR];
__device__ float g_tvp[4][BB * EE];
__device__ float g_mg[4][BB * EE];     // merge partials (prob @ emb)
__device__ float g_gm4[4][BB * G3];    // gi partials (newx @ W_ih^T)
__device__ float g_gh[4][BB * G3];     // ghh partials

typedef unsigned long long ull;
__device__ __forceinline__ ull pack2(float lo, float hi) {
    ull r; asm("mov.b64 %0, {%1, %2};" : "=l"(r) : "f"(lo), "f"(hi)); return r;
}
__device__ __forceinline__ void unpack2(ull v, float& lo, float& hi) {
    asm("mov.b64 {%0, %1}, %2;" : "=f"(lo), "=f"(hi) : "l"(v));
}
#define FMA2(acc, a, b) asm("fma.rn.f32x2 %0, %1, %2, %0;" : "+l"(acc) : "l"(a), "l"(b))

__device__ __forceinline__ float sigmf(float x) { return 1.0f / (1.0f + expf(-x)); }

__device__ __forceinline__ const float* p_gi(int b, int s) {
    int src = g_src[b * SS + s];
    return (src >= 0) ? &GI_emb[(size_t)src * G3] : &g_gi[((size_t)b * SS + s) * G3];
}
__device__ __forceinline__ const float* p_ghh(int b, int s) {
    int src = g_src[b * SS + s];
    return (src >= 0) ? &GHH_emb[(size_t)src * G3] : &g_ghh[((size_t)b * SS + s) * G3];
}
__device__ __forceinline__ const float* p_h1(int b, int s) {
    int src = g_src[b * SS + s];
    return (src >= 0) ? &H1_emb[(size_t)src * EE] : &g_h1[((size_t)b * SS + s) * EE];
}

__global__ void k_init(const int* __restrict__ tokens) {
    int b = blockIdx.x, t = threadIdx.x;
    if (t < SS) {
        g_ord[b * SS + t] = t;
        g_src[b * SS + t] = tokens[b * SS + t];
    }
}

// ======================================================================
// BEST-MEASURED core: 64x64 tile, 4x4 f32x2 reg tile, packed-A at use,
// ping-pong smem, one sync per k-tile.
// ======================================================================
struct PPBuf {
    float shA[2][16][68];
    float shB[2][16][68];
};

__device__ __forceinline__ void pp_storeA(float (*As)[68], int akg, int am, float4 ra) {
    As[akg*4+0][am] = ra.x; As[akg*4+1][am] = ra.y;
    As[akg*4+2][am] = ra.z; As[akg*4+3][am] = ra.w;
}
__device__ __forceinline__ void pp_compute(float (*As)[68], float (*Bs)[68],
                                           int tx, int ty, ull acc[4][2]) {
#pragma unroll
    for (int kk = 0; kk < 16; kk++) {
        ull b0 = *(const ull*)&Bs[kk][tx*4];
        ull b1 = *(const ull*)&Bs[kk][tx*4+2];
        float4 a = *(const float4*)&As[kk][ty*4];
        ull a0 = pack2(a.x, a.x), a1 = pack2(a.y, a.y);
        ull a2 = pack2(a.z, a.z), a3 = pack2(a.w, a.w);
        FMA2(acc[0][0], a0, b0); FMA2(acc[0][1], a0, b1);
        FMA2(acc[1][0], a1, b0); FMA2(acc[1][1], a1, b1);
        FMA2(acc[2][0], a2, b0); FMA2(acc[2][1], a2, b1);
        FMA2(acc[3][0], a3, b0); FMA2(acc[3][1], a3, b1);
    }
}

// ======================================================================
// Per-round GEMM phases (split-K partials, raw output, bias in consumers)
// ======================================================================
#define PH_BGA   0   // A=g_pair : xt<16 scores(KW), else tvec(AT);  z=4 slices of 128
#define PH_MERGE 1   // A=g_probp (K=1000), B=emb (K-major); z=4 slices of 256
#define PH_GI    2   // A=g_newx, B=W_ih; z=4 slices of 128
#define PH_GHH   3   // A=g_newh1, B=W_hh; z=4 slices of 128

__global__ __launch_bounds__(256) void k_mm(int phase,
    const float* __restrict__ emb,
    const float* __restrict__ W_ih, const float* __restrict__ W_hh)
{
    __shared__ PPBuf tb;
    int t = threadIdx.x, tx = t & 15, ty = t >> 4;
    int xt = blockIdx.x, yt = blockIdx.y, ks = blockIdx.z;

    const float* A; int lda; const float* W; float* out; int N, wld;
    int kn = 0, kb, NIT = 16, Kmax = 1 << 30;
    if (phase == PH_BGA) {
        A = g_pair; lda = 512; wld = 512; kb = ks * 128; NIT = 8;
        if (xt < 16) { W = g_KW; out = g_scp[ks]; N = RR; }
        else         { W = g_AT; out = g_tvp[ks]; N = EE; xt -= 16; }
    } else if (phase == PH_MERGE) {
        A = g_probp; lda = 1024; W = emb; wld = 512;
        out = g_mg[ks]; N = EE; kn = 1; kb = ks * 256; NIT = 16; Kmax = RR;
    } else if (phase == PH_GI) {
        A = g_newx; lda = 512; W = W_ih; wld = 512;
        out = g_gm4[ks]; N = G3; kb = ks * 128; NIT = 8;
    } else {
        A = g_newh1; lda = 512; W = W_hh; wld = 512;
        out = g_gh[ks]; N = G3; kb = ks * 128; NIT = 8;
    }
    int col0 = xt * 64, row0 = yt * 64;

    ull acc[4][2];
#pragma unroll
    for (int i = 0; i < 4; i++) { acc[i][0] = 0ULL; acc[i][1] = 0ULL; }

    int am = t >> 2, akg = t & 3;
    int gmA = row0 + am;
    int bn = t >> 2, bkg = t & 3;       // kn==0 (W is N-row-major)
    int kkB = t >> 4, ngB = t & 15;     // kn==1 (W is K-row-major)

    float4 ra = *(const float4*)&A[(size_t)gmA * lda + kb + akg * 4];
    float4 rb;
    if (kn == 0) {
        int gn = col0 + bn;
        rb = (gn < N) ? *(const float4*)&W[(size_t)gn * wld + kb + bkg * 4]
                      : make_float4(0.f, 0.f, 0.f, 0.f);
    } else {
        int k = kb + kkB;
        rb = (k < Kmax) ? *(const float4*)&W[(size_t)k * wld + col0 + ngB * 4]
                        : make_float4(0.f, 0.f, 0.f, 0.f);
    }
    pp_storeA(tb.shA[0], akg, am, ra);
    if (kn == 0) pp_storeA(tb.shB[0], bkg, bn, rb);
    else         *(float4*)&tb.shB[0][kkB][ngB * 4] = rb;
    __syncthreads();

    for (int it = 0; it < NIT; it++) {
        int cur = it & 1;
        if (it < NIT - 1) {
            int k0 = kb + (it + 1) * 16;
            ra = *(const float4*)&A[(size_t)gmA * lda + k0 + akg * 4];
            if (kn == 0) {
                int gn = col0 + bn;
                rb = (gn < N) ? *(const float4*)&W[(size_t)gn * wld + k0 + bkg * 4]
                              : make_float4(0.f, 0.f, 0.f, 0.f);
            } else {
                int k = k0 + kkB;
                rb = (k < Kmax) ? *(const float4*)&W[(size_t)k * wld + col0 + ngB * 4]
                                : make_float4(0.f, 0.f, 0.f, 0.f);
            }
        }
        pp_compute(tb.shA[cur], tb.shB[cur], tx, ty, acc);
        if (it < NIT - 1) {
            int nxt = 1 - cur;
            pp_storeA(tb.shA[nxt], akg, am, ra);
            if (kn == 0) pp_storeA(tb.shB[nxt], bkg, bn, rb);
            else         *(float4*)&tb.shB[nxt][kkB][ngB * 4] = rb;
        }
        __syncthreads();
    }
#pragma unroll
    for (int i = 0; i < 4; i++) {
        int gm = row0 + ty * 4 + i;
        float* orow = out + (size_t)gm * N;
#pragma unroll
        for (int j = 0; j < 2; j++) {
            float lo, hi;
            unpack2(acc[i][j], lo, hi);
            int c = col0 + tx * 4 + j * 2;
            if (c < N)     orow[c]     = lo;
            if (c + 1 < N) orow[c + 1] = hi;
        }
    }
}

// ============ init table GEMM, full-K with bias (Krel)
__global__ __launch_bounds__(256) void k_tab(
    const float* __restrict__ A, const float* __restrict__ W,
    const float* __restrict__ bias, float* __restrict__ out,
    int M, int N, int ldout, float scale)
{
    __shared__ PPBuf tb;
    int t = threadIdx.x, tx = t & 15, ty = t >> 4;
    int col0 = blockIdx.x * 64, row0 = blockIdx.y * 64;

    ull acc[4][2];
#pragma unroll
    for (int i = 0; i < 4; i++) { acc[i][0] = 0ULL; acc[i][1] = 0ULL; }

    int am = t >> 2, akg = t & 3;
    int gmA = row0 + am, gnB = col0 + am;

    float4 ra = (gmA < M) ? *(const float4*)&A[(size_t)gmA * 512 + akg * 4]
                          : make_float4(0.f, 0.f, 0.f, 0.f);
    float4 rb = (gnB < N) ? *(const float4*)&W[(size_t)gnB * 512 + akg * 4]
                          : make_float4(0.f, 0.f, 0.f, 0.f);
    pp_storeA(tb.shA[0], akg, am, ra);
    pp_storeA(tb.shB[0], akg, am, rb);
    __syncthreads();

    for (int it = 0; it < 32; it++) {
        int cur = it & 1;
        if (it < 31) {
            int k0 = (it + 1) * 16;
            ra = (gmA < M) ? *(const float4*)&A[(size_t)gmA * 512 + k0 + akg * 4]
                           : make_float4(0.f, 0.f, 0.f, 0.f);
            rb = (gnB < N) ? *(const float4*)&W[(size_t)gnB * 512 + k0 + akg * 4]
                           : make_float4(0.f, 0.f, 0.f, 0.f);
        }
        pp_compute(tb.shA[cur], tb.shB[cur], tx, ty, acc);
        if (it < 31) {
            int nxt = 1 - cur;
            pp_storeA(tb.shA[nxt], akg, am, ra);
            pp_storeA(tb.shB[nxt], akg, am, rb);
        }
        __syncthreads();
    }
#pragma unroll
    for (int i = 0; i < 4; i++) {
        int gm = row0 + ty * 4 + i;
        if (gm >= M) continue;
        float* orow = out + (size_t)gm * (size_t)ldout;
#pragma unroll
        for (int j = 0; j < 2; j++) {
            float lo, hi;
            unpack2(acc[i][j], lo, hi);
            int c = col0 + tx * 4 + j * 2;
            if (c < N)     orow[c]     = lo * scale + (bias ? bias[c]     : 0.f);
            if (c + 1 < N) orow[c + 1] = hi * scale + (bias ? bias[c + 1] : 0.f);
        }
    }
}

// ============ init table GEMM, split-K2, raw partials (GI / GHH tables)
__global__ __launch_bounds__(256) void k_tab2(
    const float* __restrict__ A, const float* __restrict__ W,
    float* __restrict__ out0, float* __restrict__ out1,
    int M, int N)
{
    __shared__ PPBuf tb;
    int t = threadIdx.x, tx = t & 15, ty = t >> 4;
    int col0 = blockIdx.x * 64, row0 = blockIdx.y * 64;
    int kb = blockIdx.z * 256;
    float* out = blockIdx.z ? out1 : out0;

    ull acc[4][2];
#pragma unroll
    for (int i = 0; i < 4; i++) { acc[i][0] = 0ULL; acc[i][1] = 0ULL; }

    int am = t >> 2, akg = t & 3;
    int gmA = row0 + am, gnB = col0 + am;

    float4 ra = (gmA < M) ? *(const float4*)&A[(size_t)gmA * 512 + kb + akg * 4]
                          : make_float4(0.f, 0.f, 0.f, 0.f);
    float4 rb = (gnB < N) ? *(const float4*)&W[(size_t)gnB * 512 + kb + akg * 4]
                          : make_float4(0.f, 0.f, 0.f, 0.f);
    pp_storeA(tb.shA[0], akg, am, ra);
    pp_storeA(tb.shB[0], akg, am, rb);
    __syncthreads();

    for (int it = 0; it < 16; it++) {
        int cur = it & 1;
        if (it < 15) {
            int k0 = kb + (it + 1) * 16;
            ra = (gmA < M) ? *(const float4*)&A[(size_t)gmA * 512 + k0 + akg * 4]
                           : make_float4(0.f, 0.f, 0.f, 0.f);
            rb = (gnB < N) ? *(const float4*)&W[(size_t)gnB * 512 + k0 + akg * 4]
                           : make_float4(0.f, 0.f, 0.f, 0.f);
        }
        pp_compute(tb.shA[cur], tb.shB[cur], tx, ty, acc);
        if (it < 15) {
            int nxt = 1 - cur;
            pp_storeA(tb.shA[nxt], akg, am, ra);
            pp_storeA(tb.shB[nxt], akg, am, rb);
        }
        __syncthreads();
    }
#pragma unroll
    for (int i = 0; i < 4; i++) {
        int gm = row0 + ty * 4 + i;
        if (gm >= M) continue;
        float* orow = out + (size_t)gm * (size_t)N;
#pragma unroll
        for (int j = 0; j < 2; j++) {
            float lo, hi;
            unpack2(acc[i][j], lo, hi);
            int c = col0 + tx * 4 + j * 2;
            if (c < N)     orow[c]     = lo;
            if (c + 1 < N) orow[c + 1] = hi;
        }
    }
}

// ============ KW = Krel @ Wq (B K-row-major), init-only
__global__ __launch_bounds__(256) void k_gemm_kn(
    const float* __restrict__ A, const float* __restrict__ B,
    float* __restrict__ out, int M, int N, int ldb)
{
    __shared__ PPBuf tb;
    int t = threadIdx.x, tx = t & 15, ty = t >> 4;
    int col0 = blockIdx.x * 64, row0 = blockIdx.y * 64;
    ull acc[4][2];
#pragma unroll
    for (int i = 0; i < 4; i++) { acc[i][0] = 0ULL; acc[i][1] = 0ULL; }

    int am = t >> 2, akg = t & 3;
    int gmA = row0 + am;
    int kkB = t >> 4, ngB = t & 15;

    float4 ra = (gmA < M) ? *(const float4*)&A[(size_t)gmA * 512 + akg * 4]
                          : make_float4(0.f,0.f,0.f,0.f);
    float4 rb = *(const float4*)&B[(size_t)kkB * ldb + col0 + ngB * 4];
    pp_storeA(tb.shA[0], akg, am, ra);
    *(float4*)&tb.shB[0][kkB][ngB * 4] = rb;
    __syncthreads();

    for (int it = 0; it < 32; it++) {
        int cur = it & 1;
        if (it < 31) {
            int k0 = (it + 1) * 16;
            ra = (gmA < M) ? *(const float4*)&A[(size_t)gmA * 512 + k0 + akg * 4]
                           : make_float4(0.f,0.f,0.f,0.f);
            rb = *(const float4*)&B[(size_t)(k0 + kkB) * ldb + col0 + ngB * 4];
        }
        pp_compute(tb.shA[cur], tb.shB[cur], tx, ty, acc);
        if (it < 31) {
            int nxt = 1 - cur;
            pp_storeA(tb.shA[nxt], akg, am, ra);
            *(float4*)&tb.shB[nxt][kkB][ngB * 4] = rb;
        }
        __syncthreads();
    }
#pragma unroll
    for (int i = 0; i < 4; i++) {
        int gm = row0 + ty * 4 + i;
        if (gm >= M) continue;
#pragma unroll
        for (int j = 0; j < 2; j++) {
            float lo, hi;
            unpack2(acc[i][j], lo, hi);
            int c = col0 + tx * 4 + j * 2;
            if (c < N)     out[(size_t)gm * N + c]     = lo;
            if (c + 1 < N) out[(size_t)gm * N + c + 1] = hi;
        }
    }
}

// ============ AT[m][n] = sum_k Wk[k][m] * Wq[k][n]  (both K-row-major), init-only
__global__ __launch_bounds__(256) void k_gemm_tn(
    const float* __restrict__ P, const float* __restrict__ Q, float* __restrict__ out)
{
    __shared__ PPBuf tb;
    int t = threadIdx.x, tx = t & 15, ty = t >> 4;
    int col0 = blockIdx.x * 64, row0 = blockIdx.y * 64;
    ull acc[4][2];
#pragma unroll
    for (int i = 0; i < 4; i++) { acc[i][0] = 0ULL; acc[i][1] = 0ULL; }
    int kk0 = t >> 4, g = t & 15;

    float4 ra = *(const float4*)&P[(size_t)kk0 * 512 + row0 + g * 4];
    float4 rb = *(const float4*)&Q[(size_t)kk0 * 512 + col0 + g * 4];
    *(float4*)&tb.shA[0][kk0][g * 4] = ra;
    *(float4*)&tb.shB[0][kk0][g * 4] = rb;
    __syncthreads();

    for (int it = 0; it < 32; it++) {
        int cur = it & 1;
        if (it < 31) {
            int k0 = (it + 1) * 16;
            ra = *(const float4*)&P[(size_t)(k0 + kk0) * 512 + row0 + g * 4];
            rb = *(const float4*)&Q[(size_t)(k0 + kk0) * 512 + col0 + g * 4];
        }
        pp_compute(tb.shA[cur], tb.shB[cur], tx, ty, acc);
        if (it < 31) {
            int nxt = 1 - cur;
            *(float4*)&tb.shA[nxt][kk0][g * 4] = ra;
            *(float4*)&tb.shB[nxt][kk0][g * 4] = rb;
        }
        __syncthreads();
    }
#pragma unroll
    for (int i = 0; i < 4; i++) {
        int gm = row0 + ty * 4 + i;
#pragma unroll
        for (int j = 0; j < 2; j++) {
            float lo, hi;
            unpack2(acc[i][j], lo, hi);
            int c = col0 + tx * 4 + j * 2;
            out[(size_t)gm * 512 + c]     = lo;
            out[(size_t)gm * 512 + c + 1] = hi;
        }
    }
}

__global__ void k_wc(const float* __restrict__ Wq, const float* __restrict__ bq,
                     const float* __restrict__ Wk, const float* __restrict__ bk) {
    __shared__ float red[256];
    int t = threadIdx.x;
    int i = blockIdx.x * 256 + t;
    float acc = 0.f;
    for (int n = 0; n < EE; n++)
        acc += Wq[(size_t)n * EE + i] * bk[n] + Wk[(size_t)n * EE + i] * bq[n];
    g_wvec[i] = acc;
    if (blockIdx.x == 0) {
        float p = 0.f;
        for (int n = t; n < EE; n += 256) p += bq[n] * bk[n];
        red[t] = p; __syncthreads();
        for (int s = 128; s > 0; s >>= 1) { if (t < s) red[t] += red[t + s]; __syncthreads(); }
        if (t == 0) g_c0[0] = red[0];
    }
}

// h1emb: finalize GI = GIa + GIb + b_ih (write), then H1 from it.
__global__ void k_h1emb(const float* __restrict__ b_ih, const float* __restrict__ b_hh) {
    int tk = blockIdx.x;
    float* gi = &GI_emb[(size_t)tk * G3];
    const float* gs = &g_tscr[(size_t)tk * G3];
    for (int e = threadIdx.x; e < G3; e += blockDim.x)
        gi[e] = gi[e] + gs[e] + b_ih[e];
    __syncthreads();
    for (int e = threadIdx.x; e < EE; e += blockDim.x) {
        float r = sigmf(gi[e] + b_hh[e]);
        float z = sigmf(gi[EE + e] + b_hh[EE + e]);
        float n = tanhf(gi[2 * EE + e] + r * b_hh[2 * EE + e]);
        H1_emb[(size_t)tk * EE + e] = (1.f - z) * n;
    }
}

// finalize GHH = GHHa + GHHb + b_hh
__global__ void k_add(const float* __restrict__ b_hh) {
    int tk = blockIdx.x;
    float* o = &GHH_emb[(size_t)tk * G3];
    const float* s = &g_tscr[(size_t)tk * G3];
    for (int e = threadIdx.x; e < G3; e += blockDim.x)
        o[e] = o[e] + s[e] + b_hh[e];
}

__global__ void k_cinit(const float* __restrict__ bq) {
    int r = blockIdx.x * 8 + (threadIdx.x >> 5);
    int lane = threadIdx.x & 31;
    if (r >= RR) return;
    float s = 0.f;
    for (int e = lane; e < EE; e += 32) s += bq[e] * g_Krel[(size_t)r * EE + e];
#pragma unroll
    for (int off = 16; off > 0; off >>= 1) s += __shfl_down_sync(0xffffffffu, s, off);
    if (lane == 0) g_cs[r] = NSCALE * s;
}

// =================== round-phase kernels ===================

__device__ __forceinline__ float pair_elem(const float* gi, const float* gh,
                                           const float* h1, int e) {
    float r = sigmf(gi[e] + gh[e]);
    float z = sigmf(gi[EE + e] + gh[EE + e]);
    float n = tanhf(gi[2 * EE + e] + r * gh[2 * EE + e]);
    return (1.f - z) * n + z * h1[e];
}

__global__ void k_pairsel(const float* __restrict__ wfc, const float* __restrict__ bfc,
                          const float* __restrict__ b_hh,
                          int npairs, int zloss, float* __restrict__ loss_out, int first) {
    int b = blockIdx.x, t = threadIdx.x;
    int w = t >> 5, lane = t & 31;
    __shared__ int sord[SS];
    __shared__ float sps[SS];
    __shared__ int sbestj;

    // finalize previous round's ghh partials into g_ghh[b][prev_dslot]
    if (!first) {
        int slot = g_dslot[b];
        float* orow = &g_ghh[((size_t)b * SS + slot) * G3];
        const float* gA = &g_gh[0][(size_t)b * G3];
        const float* gB = &g_gh[1][(size_t)b * G3];
        const float* gC = &g_gh[2][(size_t)b * G3];
        const float* gD = &g_gh[3][(size_t)b * G3];
        for (int e = t; e < G3; e += 256)
            orow[e] = gA[e] + gB[e] + gC[e] + gD[e] + b_hh[e];
        __syncthreads();
    }

    if (t < SS) {
        sord[t] = g_ord[b * SS + t];
        sps[t]  = g_pscore[b * SS + t];
    }
    int prev_sel = g_sel[b];
    __syncthreads();

    int j0 = -1, j1 = -1;
    if (first) {
        j0 = w;  j1 = w + 8;
        if (j0 >= npairs) j0 = -1;
        if (j1 >= npairs) j1 = -1;
    } else {
        int cnt = 0, jj[2];
        if (prev_sel - 1 >= 0 && prev_sel - 1 < npairs) jj[cnt++] = prev_sel - 1;
        if (prev_sel >= 0 && prev_sel < npairs)         jj[cnt++] = prev_sel;
        if (w < cnt) j0 = jj[w];
    }
#pragma unroll
    for (int rep = 0; rep < 2; rep++) {
        int j = (rep == 0) ? j0 : j1;
        if (j >= 0) {
            const float* gi = p_gi(b, sord[j + 1]);
            const float* gh = p_ghh(b, sord[j]);
            const float* h1 = p_h1(b, sord[j]);
            float s = 0.f;
            for (int e = lane; e < EE; e += 32)
                s += pair_elem(gi, gh, h1, e) * wfc[e];
#pragma unroll
            for (int off = 16; off > 0; off >>= 1)
                s += __shfl_down_sync(0xffffffffu, s, off);
            if (lane == 0) {
                float sc = sigmf(s + bfc[0]);
                sps[j] = sc;
                g_pscore[b * SS + j] = sc;
            }
        }
    }
    __syncthreads();

    if (t == 0) {
        int bj = 0; float bs = sps[0];
        for (int j = 1; j < npairs; j++)
            if (sps[j] > bs) { bs = sps[j]; bj = j; }
        sbestj = bj;
        g_sel[b] = bj;
        if (zloss >= 0) loss_out[b * SS + zloss] = 0.f;
    }
    __syncthreads();
    int j = sbestj;
    const float* gi = p_gi(b, sord[j + 1]);
    const float* gh = p_ghh(b, sord[j]);
    const float* h1 = p_h1(b, sord[j]);
    for (int e = t; e < EE; e += 256)
        g_pair[(size_t)b * EE + e] = pair_elem(gi, gh, h1, e);
}

__device__ __forceinline__ float bsum(float v, float* red, int t) {
    red[t] = v; __syncthreads();
    for (int s = 128; s > 0; s >>= 1) { if (t < s) red[t] += red[t + s]; __syncthreads(); }
    return red[0];
}
__device__ __forceinline__ float bmax(float v, float* red, int t) {
    red[t] = v; __syncthreads();
    for (int s = 128; s > 0; s >>= 1) { if (t < s) red[t] = fmaxf(red[t], red[t + s]); __syncthreads(); }
    return red[0];
}

__global__ void k_softmax(int lossidx, int L, int do_book,
                          float* __restrict__ loss_out, float* __restrict__ scores_out) {
    int b = blockIdx.x, t = threadIdx.x;
    __shared__ float red[256];
    const float* pp  = &g_pair[(size_t)b * EE];
    const float* t0 = &g_tvp[0][(size_t)b * EE];
    const float* t1 = &g_tvp[1][(size_t)b * EE];
    const float* t2 = &g_tvp[2][(size_t)b * EE];
    const float* t3 = &g_tvp[3][(size_t)b * EE];
    const float* s0 = &g_scp[0][(size_t)b * RR];
    const float* s1 = &g_scp[1][(size_t)b * RR];
    const float* s2 = &g_scp[2][(size_t)b * RR];
    const float* s3 = &g_scp[3][(size_t)b * RR];

    float part = 0.f;
    for (int e = t; e < EE; e += 256)
        part += (t0[e] + t1[e] + t2[e] + t3[e] + g_wvec[e]) * pp[e];
    float c1000 = (bsum(part, red, t) + g_c0[0]) * NSCALE;
    __syncthreads();

    float m = -3.4e38f;
    for (int k = t; k <= RR; k += 256) {
        float v = (k < RR) ? ((s0[k] + s1[k] + s2[k] + s3[k]) * NSCALE + g_cs[k]) : c1000;
        m = fmaxf(m, v);
    }
    m = bmax(m, red, t);
    __syncthreads();

    float se = 0.f, sv = 0.f;
    for (int k = t; k <= RR; k += 256) {
        float raw = (k < RR) ? ((s0[k] + s1[k] + s2[k] + s3[k]) * NSCALE + g_cs[k]) : c1000;
        float v = raw - m;
        float ev = expf(v);
        se += ev; sv += ev * v;
    }
    float Z = bsum(se, red, t);
    __syncthreads();
    float S2 = bsum(sv, red, t);
    if (t == 0) {
        loss_out[b * SS + lossidx] = logf(Z) - S2 / Z;
        g_pp[b] = expf(c1000 - m) / Z;
    }

    float* pr = &g_probp[(size_t)b * 1024];
    for (int k = t; k < 1024; k += 256) {
        if (k < RR) {
            float raw = (s0[k] + s1[k] + s2[k] + s3[k]) * NSCALE + g_cs[k];
            pr[k] = expf(raw - m) / Z;
        } else {
            pr[k] = 0.f;
        }
    }
    if (scores_out) {
        for (int k = t; k <= RR; k += 256) {
            float raw = (k < RR) ? ((s0[k] + s1[k] + s2[k] + s3[k]) * NSCALE + g_cs[k]) : c1000;
            scores_out[(size_t)b * (RR + 1) + k] = raw;
        }
    }
    if (t == 0 && do_book) {
        int sel = g_sel[b];
        int* ord = &g_ord[b * SS];
        float* ps = &g_pscore[b * SS];
        int slot = ord[sel];
        g_dslot[b] = slot;
        g_src[b * SS + slot] = -1;
        for (int i = sel + 1; i < L - 1; i++) { ord[i] = ord[i + 1]; ps[i] = ps[i + 1]; }
    }
}

// mfin: newx = sum of 4 merge partials + pp * pair
__global__ void k_mfin() {
    int b = blockIdx.x, t = threadIdx.x;
    float pp = g_pp[b];
    const float* m0 = &g_mg[0][(size_t)b * EE];
    const float* m1 = &g_mg[1][(size_t)b * EE];
    const float* m2 = &g_mg[2][(size_t)b * EE];
    const float* m3 = &g_mg[3][(size_t)b * EE];
    const float* pr = &g_pair[(size_t)b * EE];
    float* o = &g_newx[(size_t)b * EE];
    for (int e = t; e < EE; e += 256)
        o[e] = m0[e] + m1[e] + m2[e] + m3[e] + pp * pr[e];
}

// h1fin: gi = sum 4 GI partials + b_ih, scatter, compute h1
__global__ void k_h1fin(const float* __restrict__ b_ih, const float* __restrict__ b_hh) {
    __shared__ __align__(16) float sgi[G3];
    int b = blockIdx.x, t = threadIdx.x;
    int slot = g_dslot[b];
    float* orow = &g_gi[((size_t)b * SS + slot) * G3];
    const float* m0 = &g_gm4[0][(size_t)b * G3];
    const float* m1 = &g_gm4[1][(size_t)b * G3];
    const float* m2 = &g_gm4[2][(size_t)b * G3];
    const float* m3 = &g_gm4[3][(size_t)b * G3];
    for (int e = t; e < G3; e += 256) {
        float v = m0[e] + m1[e] + m2[e] + m3[e] + b_ih[e];
        sgi[e] = v;
        orow[e] = v;
    }
    __syncthreads();
    for (int e = t; e < EE; e += 256) {
        float r = sigmf(sgi[e] + b_hh[e]);
        float z = sigmf(sgi[EE + e] + b_hh[EE + e]);
        float n = tanhf(sgi[2 * EE + e] + r * b_hh[2 * EE + e]);
        float h = (1.f - z) * n;
        g_h1[((size_t)b * SS + slot) * EE + e] = h;
        g_newh1[(size_t)b * EE + e] = h;
    }
}

// ---------------- host ----------------
extern "C" void kernel_launch(void* const* d_in, const int* in_sizes, int n_in,
                              void* d_out, int out_size) {
    const int*   tokens = (const int*)  d_in[0];
    const float* emb    = (const float*)d_in[1];
    const float* W_ih   = (const float*)d_in[2];
    const float* W_hh   = (const float*)d_in[3];
    const float* b_ih   = (const float*)d_in[4];
    const float* b_hh   = (const float*)d_in[5];
    const float* w_fc   = (const float*)d_in[6];
    const float* b_fc   = (const float*)d_in[7];
    const float* Wq     = (const float*)d_in[8];
    const float* bq     = (const float*)d_in[9];
    const float* Wk     = (const float*)d_in[10];
    const float* bk     = (const float*)d_in[11];

    float* out_scores = (float*)d_out;                         // 128 x 1001
    float* out_loss   = (float*)d_out + (size_t)BB * (RR + 1); // 128 x 16

    float *GI, *H1, *GHH, *TS, *Krel, *KW, *AT;
    cudaGetSymbolAddress((void**)&GI, GI_emb);
    cudaGetSymbolAddress((void**)&H1, H1_emb);
    cudaGetSymbolAddress((void**)&GHH, GHH_emb);
    cudaGetSymbolAddress((void**)&TS, g_tscr);
    cudaGetSymbolAddress((void**)&Krel, g_Krel);
    cudaGetSymbolAddress((void**)&KW, g_KW);
    cudaGetSymbolAddress((void**)&AT, g_AT);

    // ---- init (once per call) ----
    k_init<<<BB, 32>>>(tokens);
    k_tab2<<<dim3(24, 16, 2), 256>>>(emb, W_ih, GI, TS, RR, G3);
    k_h1emb<<<RR, 256>>>(b_ih, b_hh);                  // GI += TS + b_ih; H1
    k_tab2<<<dim3(24, 16, 2), 256>>>(H1, W_hh, GHH, TS, RR, G3);
    k_add<<<RR, 256>>>(b_hh);                          // GHH += TS + b_hh
    k_tab<<<dim3(8, 16), 256>>>(emb, Wk, bk, Krel, RR, EE, EE, 1.f);
    k_gemm_kn<<<dim3(8, 16), 256>>>(Krel, Wq, KW, RR, EE, EE);
    k_cinit<<<125, 256>>>(bq);
    k_gemm_tn<<<dim3(8, 8), 256>>>(Wk, Wq, AT);
    k_wc<<<2, 256>>>(Wq, bq, Wk, bk);

    // ---- 14 merge rounds ----
    for (int i = 0; i < 14; i++) {
        int L = SS - i;
        k_pairsel<<<BB, 256>>>(w_fc, b_fc, b_hh, L - 1, -1, out_loss, i == 0);
        k_mm<<<dim3(24, 2, 4), 256>>>(PH_BGA, emb, W_ih, W_hh);   // scores + tvec
        k_softmax<<<BB, 256>>>(i, L, 1, out_loss, NULL);
        k_mm<<<dim3(8, 2, 4), 256>>>(PH_MERGE, emb, W_ih, W_hh);  // prob @ emb
        k_mfin<<<BB, 256>>>();
        k_mm<<<dim3(24, 2, 4), 256>>>(PH_GI, emb, W_ih, W_hh);    // newx @ W_ih^T
        k_h1fin<<<BB, 256>>>(b_ih, b_hh);
        k_mm<<<dim3(24, 2, 4), 256>>>(PH_GHH, emb, W_ih, W_hh);   // newh1 @ W_hh^T
    }
    // ---- final round (L=2) + output attention ----
    k_pairsel<<<BB, 256>>>(w_fc, b_fc, b_hh, 1, 14, out_loss, 0);
    k_mm<<<dim3(24, 2, 4), 256>>>(PH_BGA, emb, W_ih, W_hh);
    k_softmax<<<BB, 256>>>(15, 0, 0, out_loss, out_scores);
}